// round 9
// baseline (speedup 1.0000x reference)
#include <cuda_runtime.h>
#include <cuda_bf16.h>
#include <cstdint>

// GCN 2-layer, N=500000, E=16000000 — packed dst-binned formulation, v7.
// v6 + last-arrival fusion: nodeA fused into cnt, nodeB fused into s1,
// detect fused into init. 5 launches total.
//
//   deg_i = indeg(i) + 1;  dis_i = rsqrt(deg_i);  p_j = dis_j * x_j
//   s_i = dis_i * ( sum_{j->i} p_j + dis_i*x_i )
//   h_i[k] = relu(s_i*W1[k] + b1[k]);  q_i = dis_i * (h_i @ W2)
//   out_i = dis_i * sum_{j->i} q_j + (dis_i*q_i + b2)

static constexpr int N_MAX   = 500000;
static constexpr int SHIFT   = 12;
static constexpr int SLICE   = 1 << SHIFT;           // 4096
static constexpr int NB      = 128;                  // >= ceil(500000/4096)=123
static constexpr int CAP     = 139264;               // mean 130081 + ~25 sigma
static constexpr int BT      = 512;                  // bin threads
static constexpr int PER     = 8;                    // edges per bin thread
static constexpr int CHUNK   = BT * PER;             // 4096
static constexpr int REG_CAP = 80;                   // mean 32/bucket + 8.4 sigma
static constexpr int SPLIT   = 8;                    // CTAs per bucket

__device__ int    g_is64;
__device__ int    g_cursor[NB];
__device__ int    g_arr_cnt[NB];                     // arrival counters (cnt phase)
__device__ int    g_arr_s1[NB];                      // arrival counters (s1 phase)
__device__ int    g_binned[(size_t)NB * CAP];        // packed edges (~71 MB)
__device__ int    g_cnt[N_MAX];                      // indegree
__device__ float  g_t[N_MAX];                        // layer-1 accumulator
__device__ float  g_dis[N_MAX];
__device__ float  g_p[N_MAX];                        // dis_j * x_j
__device__ float2 g_q[N_MAX];                        // dis_i * (h_i @ W2)

// ---------------------------------------------------------------- init: zero + dtype probe
__global__ void k_init(const long long* __restrict__ ei, int n_check, int N) {
    int i = blockIdx.x * blockDim.x + threadIdx.x;
    if (i < N) {
        g_cnt[i] = 0;
        g_t[i]   = 0.0f;
    }
    if (i < NB) {
        g_cursor[i]  = 0;
        g_arr_cnt[i] = 0;
        g_arr_s1[i]  = 0;
    }
    if (i == 0) {
        int ok = 1;
        for (int k = 0; k < n_check; k++) {
            long long v = ei[k];
            if (v < 0 || v >= (long long)N) { ok = 0; break; }
        }
        g_is64 = ok;
    }
}

// ---------------------------------------------------------------- binning
__global__ __launch_bounds__(BT) void k_bin(const void* __restrict__ edge, int E) {
    __shared__ int region[NB * REG_CAP];   // 40 KB: per-bucket slots
    __shared__ int lcur[NB];
    __shared__ int gbase[NB];

    const int t = threadIdx.x;
    const long long base = (long long)blockIdx.x * CHUNK;
    if (base >= E) return;

    if (t < NB) lcur[t] = 0;
    __syncthreads();

    const bool is64 = (g_is64 != 0);
    if (is64) {
        const long long* src = (const long long*)edge;
        const long long* dst = src + E;
#pragma unroll
        for (int k = 0; k < PER; k++) {
            long long idx = base + k * BT + t;
            if (idx < E) {
                int s = (int)__ldcs(&src[idx]);
                int d = (int)__ldcs(&dst[idx]);
                int b = d >> SHIFT;
                int pos = atomicAdd(&lcur[b], 1);
                if (pos < REG_CAP)
                    region[b * REG_CAP + pos] = s | ((d & (SLICE - 1)) << 19);
            }
        }
    } else {
        const int* src = (const int*)edge;
        const int* dst = src + E;
#pragma unroll
        for (int k = 0; k < PER; k++) {
            long long idx = base + k * BT + t;
            if (idx < E) {
                int s = __ldcs(&src[idx]);
                int d = __ldcs(&dst[idx]);
                int b = d >> SHIFT;
                int pos = atomicAdd(&lcur[b], 1);
                if (pos < REG_CAP)
                    region[b * REG_CAP + pos] = s | ((d & (SLICE - 1)) << 19);
            }
        }
    }
    __syncthreads();

    if (t < NB) {
        int c = min(lcur[t], REG_CAP);
        lcur[t]  = c;
        gbase[t] = (c > 0) ? atomicAdd(&g_cursor[t], c) : 0;
    }
    __syncthreads();

    const int w = t >> 5, lane = t & 31;
    for (int b = w; b < NB; b += 16) {
        const int c  = lcur[b];
        const int gb = gbase[b];
        const long long gp0 = (long long)b * CAP;
        for (int j = lane; j < c; j += 32)
            __stcs(&g_binned[gp0 + min(gb + j, CAP - 1)], region[b * REG_CAP + j]);
    }
}

// ---------------------------------------------------------------- degree + nodeA (last arrival)
__global__ __launch_bounds__(512) void k_cnt(const float* __restrict__ x, int N) {
    __shared__ int cnt[SLICE];
    __shared__ int is_last;
    const int b    = blockIdx.x / SPLIT;
    const int part = blockIdx.x % SPLIT;
    const int t    = threadIdx.x;
    for (int i = t; i < SLICE; i += 512) cnt[i] = 0;
    __syncthreads();

    const int ne = min(g_cursor[b], CAP);
    const int s0 = (int)((long long)ne * part / SPLIT);
    const int s1 = (int)((long long)ne * (part + 1) / SPLIT);
    const int* eb = g_binned + (size_t)b * CAP;

    int i = s0 + t;
    for (; i + 3 * 512 < s1; i += 4 * 512) {
        int pk0 = __ldcs(&eb[i]);
        int pk1 = __ldcs(&eb[i + 512]);
        int pk2 = __ldcs(&eb[i + 1024]);
        int pk3 = __ldcs(&eb[i + 1536]);
        atomicAdd(&cnt[(pk0 >> 19) & (SLICE - 1)], 1);
        atomicAdd(&cnt[(pk1 >> 19) & (SLICE - 1)], 1);
        atomicAdd(&cnt[(pk2 >> 19) & (SLICE - 1)], 1);
        atomicAdd(&cnt[(pk3 >> 19) & (SLICE - 1)], 1);
    }
    for (; i < s1; i += 512)
        atomicAdd(&cnt[(__ldcs(&eb[i]) >> 19) & (SLICE - 1)], 1);
    __syncthreads();

    const int nbase = b << SHIFT;
    for (int l = t; l < SLICE; l += 512)
        if (cnt[l]) atomicAdd(&g_cnt[nbase + l], cnt[l]);

    // arrival: last CTA of this bucket computes dis, p
    __threadfence();
    __syncthreads();
    if (t == 0) is_last = (atomicAdd(&g_arr_cnt[b], 1) == SPLIT - 1) ? 1 : 0;
    __syncthreads();
    if (is_last) {
        for (int l = t; l < SLICE; l += 512) {
            int node = nbase + l;
            if (node < N) {
                float dis = rsqrtf((float)(__ldcg(&g_cnt[node]) + 1)); // +1 self loop
                g_dis[node] = dis;
                g_p[node]   = dis * x[node];
            }
        }
    }
}

// ---------------------------------------------------------------- layer-1 scatter + nodeB (last arrival)
__global__ __launch_bounds__(512) void k_s1(const float* __restrict__ x,
                                            const float* __restrict__ W1,
                                            const float* __restrict__ b1,
                                            const float* __restrict__ W2,
                                            const float* __restrict__ b2,
                                            float2* __restrict__ out, int N) {
    __shared__ float acc[SLICE];
    __shared__ int is_last;
    const int b    = blockIdx.x / SPLIT;
    const int part = blockIdx.x % SPLIT;
    const int t    = threadIdx.x;
    for (int i = t; i < SLICE; i += 512) acc[i] = 0.0f;
    __syncthreads();

    const int ne = min(g_cursor[b], CAP);
    const int s0 = (int)((long long)ne * part / SPLIT);
    const int s1 = (int)((long long)ne * (part + 1) / SPLIT);
    const int* eb = g_binned + (size_t)b * CAP;

    int i = s0 + t;
    for (; i + 3 * 512 < s1; i += 4 * 512) {
        int pk0 = __ldcs(&eb[i]);
        int pk1 = __ldcs(&eb[i + 512]);
        int pk2 = __ldcs(&eb[i + 1024]);
        int pk3 = __ldcs(&eb[i + 1536]);
        float p0 = __ldg(&g_p[pk0 & 0x7FFFF]);
        float p1 = __ldg(&g_p[pk1 & 0x7FFFF]);
        float p2 = __ldg(&g_p[pk2 & 0x7FFFF]);
        float p3 = __ldg(&g_p[pk3 & 0x7FFFF]);
        atomicAdd(&acc[(pk0 >> 19) & (SLICE - 1)], p0);
        atomicAdd(&acc[(pk1 >> 19) & (SLICE - 1)], p1);
        atomicAdd(&acc[(pk2 >> 19) & (SLICE - 1)], p2);
        atomicAdd(&acc[(pk3 >> 19) & (SLICE - 1)], p3);
    }
    for (; i < s1; i += 512) {
        int pk = __ldcs(&eb[i]);
        atomicAdd(&acc[(pk >> 19) & (SLICE - 1)], __ldg(&g_p[pk & 0x7FFFF]));
    }
    __syncthreads();

    const int nbase = b << SHIFT;
    for (int l = t; l < SLICE; l += 512)
        if (acc[l] != 0.0f) atomicAdd(&g_t[nbase + l], acc[l]);

    // arrival: last CTA runs the MLP for this bucket's nodes
    __threadfence();
    __syncthreads();
    if (t == 0) is_last = (atomicAdd(&g_arr_s1[b], 1) == SPLIT - 1) ? 1 : 0;
    __syncthreads();
    if (is_last) {
        float w1[8], bb1[8], w20[8], w21[8];
#pragma unroll
        for (int k = 0; k < 8; k++) {
            w1[k]  = __ldg(&W1[k]);
            bb1[k] = __ldg(&b1[k]);
            w20[k] = __ldg(&W2[2 * k + 0]);
            w21[k] = __ldg(&W2[2 * k + 1]);
        }
        float b20 = __ldg(&b2[0]), b21 = __ldg(&b2[1]);
        for (int l = t; l < SLICE; l += 512) {
            int node = nbase + l;
            if (node < N) {
                float dis = g_dis[node];
                float s   = dis * (__ldcg(&g_t[node]) + dis * x[node]);
                float q0 = 0.0f, q1 = 0.0f;
#pragma unroll
                for (int k = 0; k < 8; k++) {
                    float h = fmaxf(fmaf(s, w1[k], bb1[k]), 0.0f);
                    q0 = fmaf(h, w20[k], q0);
                    q1 = fmaf(h, w21[k], q1);
                }
                q0 *= dis; q1 *= dis;
                g_q[node] = make_float2(q0, q1);
                out[node] = make_float2(fmaf(dis, q0, b20),
                                        fmaf(dis, q1, b21));
            }
        }
    }
}

// ---------------------------------------------------------------- layer-2 scatter -> out
__device__ __forceinline__ void red_add_v2(float2* addr, float a, float b) {
    asm volatile("red.global.add.v2.f32 [%0], {%1, %2};"
                 :: "l"(addr), "f"(a), "f"(b) : "memory");
}

__global__ __launch_bounds__(512) void k_s2(float2* __restrict__ out, int N) {
    __shared__ float ux[SLICE];
    __shared__ float uy[SLICE];
    const int b    = blockIdx.x / SPLIT;
    const int part = blockIdx.x % SPLIT;
    const int t    = threadIdx.x;
    for (int i = t; i < SLICE; i += 512) { ux[i] = 0.0f; uy[i] = 0.0f; }
    __syncthreads();

    const int ne = min(g_cursor[b], CAP);
    const int s0 = (int)((long long)ne * part / SPLIT);
    const int s1 = (int)((long long)ne * (part + 1) / SPLIT);
    const int* eb = g_binned + (size_t)b * CAP;

    int i = s0 + t;
    for (; i + 3 * 512 < s1; i += 4 * 512) {
        int pk0 = __ldcs(&eb[i]);
        int pk1 = __ldcs(&eb[i + 512]);
        int pk2 = __ldcs(&eb[i + 1024]);
        int pk3 = __ldcs(&eb[i + 1536]);
        float2 q0 = __ldg(&g_q[pk0 & 0x7FFFF]);
        float2 q1 = __ldg(&g_q[pk1 & 0x7FFFF]);
        float2 q2 = __ldg(&g_q[pk2 & 0x7FFFF]);
        float2 q3 = __ldg(&g_q[pk3 & 0x7FFFF]);
        int l0 = (pk0 >> 19) & (SLICE - 1), l1 = (pk1 >> 19) & (SLICE - 1);
        int l2 = (pk2 >> 19) & (SLICE - 1), l3 = (pk3 >> 19) & (SLICE - 1);
        atomicAdd(&ux[l0], q0.x); atomicAdd(&uy[l0], q0.y);
        atomicAdd(&ux[l1], q1.x); atomicAdd(&uy[l1], q1.y);
        atomicAdd(&ux[l2], q2.x); atomicAdd(&uy[l2], q2.y);
        atomicAdd(&ux[l3], q3.x); atomicAdd(&uy[l3], q3.y);
    }
    for (; i < s1; i += 512) {
        int pk = __ldcs(&eb[i]);
        float2 q = __ldg(&g_q[pk & 0x7FFFF]);
        int l = (pk >> 19) & (SLICE - 1);
        atomicAdd(&ux[l], q.x); atomicAdd(&uy[l], q.y);
    }
    __syncthreads();

    const int nbase = b << SHIFT;
    for (int l = t; l < SLICE; l += 512) {
        int node = nbase + l;
        if (node < N && (ux[l] != 0.0f || uy[l] != 0.0f)) {
            float dis = g_dis[node];
            red_add_v2(&out[node], dis * ux[l], dis * uy[l]);
        }
    }
}

// ================================================================ launch
extern "C" void kernel_launch(void* const* d_in, const int* in_sizes, int n_in,
                              void* d_out, int out_size) {
    const float* x  = (const float*)d_in[0];
    const void*  ei = d_in[1];            // [2, E]: src then dst; int32 or int64
    const float* W1 = (const float*)d_in[2];
    const float* b1 = (const float*)d_in[3];
    const float* W2 = (const float*)d_in[4];
    const float* b2 = (const float*)d_in[5];

    const int N  = in_sizes[0];           // 500000
    const int E  = in_sizes[1] / 2;       // 16000000
    int nb = (N + SLICE - 1) >> SHIFT;    // 123
    if (nb > NB) nb = NB;

    const int nb_bin  = (int)(((long long)E + CHUNK - 1) / CHUNK);
    const int nb_node = (N + 255) / 256;

    k_init<<<nb_node, 256>>>((const long long*)ei, 64, N);
    k_bin <<<nb_bin, BT>>>(ei, E);
    k_cnt <<<nb * SPLIT, 512>>>(x, N);
    k_s1  <<<nb * SPLIT, 512>>>(x, W1, b1, W2, b2, (float2*)d_out, N);
    k_s2  <<<nb * SPLIT, 512>>>((float2*)d_out, N);
}

// round 10
// speedup vs baseline: 1.0670x; 1.0670x over previous
#include <cuda_runtime.h>
#include <cuda_bf16.h>
#include <cstdint>

// GCN 2-layer, N=500000, E=16000000 — packed dst-binned formulation, v8.
// = v6 (best, 282.7us) with batch-8 two-phase ILP in the gather kernels
// (s1, s2) to break the binned-load -> gather -> atomic latency chain.
//
//   deg_i = indeg(i) + 1;  dis_i = rsqrt(deg_i);  p_j = dis_j * x_j
//   s_i = dis_i * ( sum_{j->i} p_j + dis_i*x_i )
//   h_i[k] = relu(s_i*W1[k] + b1[k]);  q_i = dis_i * (h_i @ W2)
//   out_i = dis_i * sum_{j->i} q_j + (dis_i*q_i + b2)

static constexpr int N_MAX   = 500000;
static constexpr int SHIFT   = 12;
static constexpr int SLICE   = 1 << SHIFT;           // 4096
static constexpr int NB      = 128;                  // >= ceil(500000/4096)=123
static constexpr int CAP     = 139264;               // mean 130081 + ~25 sigma
static constexpr int BT      = 512;                  // bin threads
static constexpr int PER     = 8;                    // edges per bin thread
static constexpr int CHUNK   = BT * PER;             // 4096
static constexpr int REG_CAP = 80;                   // mean 32/bucket + 8.4 sigma
static constexpr int SPLIT   = 8;                    // CTAs per bucket

__device__ int    g_is64;
__device__ int    g_cursor[NB];
__device__ int    g_binned[(size_t)NB * CAP];        // packed edges (~71 MB)
__device__ int    g_cnt[N_MAX];                      // indegree
__device__ float  g_t[N_MAX];                        // layer-1 accumulator
__device__ float  g_dis[N_MAX];
__device__ float  g_p[N_MAX];                        // dis_j * x_j
__device__ float2 g_q[N_MAX];                        // dis_i * (h_i @ W2)

// ---------------------------------------------------------------- dtype probe (+cursor zero)
__global__ void k_detect(const long long* __restrict__ ei, int n_check, int N) {
    int t = threadIdx.x;
    if (t < NB) g_cursor[t] = 0;
    if (t == 0) {
        int ok = 1;
        for (int i = 0; i < n_check; i++) {
            long long v = ei[i];
            if (v < 0 || v >= (long long)N) { ok = 0; break; }
        }
        g_is64 = ok;
    }
}

// ---------------------------------------------------------------- zero state
__global__ void k_zero(int N) {
    int i = blockIdx.x * blockDim.x + threadIdx.x;
    if (i < N) {
        g_cnt[i] = 0;
        g_t[i]   = 0.0f;
    }
}

// ---------------------------------------------------------------- binning (v4/v6 config)
__global__ __launch_bounds__(BT) void k_bin(const void* __restrict__ edge, int E) {
    __shared__ int region[NB * REG_CAP];   // 40 KB: per-bucket slots
    __shared__ int lcur[NB];
    __shared__ int gbase[NB];

    const int t = threadIdx.x;
    const long long base = (long long)blockIdx.x * CHUNK;
    if (base >= E) return;

    if (t < NB) lcur[t] = 0;
    __syncthreads();

    const bool is64 = (g_is64 != 0);
    if (is64) {
        const long long* src = (const long long*)edge;
        const long long* dst = src + E;
#pragma unroll
        for (int k = 0; k < PER; k++) {
            long long idx = base + k * BT + t;
            if (idx < E) {
                int s = (int)__ldcs(&src[idx]);
                int d = (int)__ldcs(&dst[idx]);
                int b = d >> SHIFT;
                int pos = atomicAdd(&lcur[b], 1);
                if (pos < REG_CAP)
                    region[b * REG_CAP + pos] = s | ((d & (SLICE - 1)) << 19);
            }
        }
    } else {
        const int* src = (const int*)edge;
        const int* dst = src + E;
#pragma unroll
        for (int k = 0; k < PER; k++) {
            long long idx = base + k * BT + t;
            if (idx < E) {
                int s = __ldcs(&src[idx]);
                int d = __ldcs(&dst[idx]);
                int b = d >> SHIFT;
                int pos = atomicAdd(&lcur[b], 1);
                if (pos < REG_CAP)
                    region[b * REG_CAP + pos] = s | ((d & (SLICE - 1)) << 19);
            }
        }
    }
    __syncthreads();

    if (t < NB) {
        int c = min(lcur[t], REG_CAP);
        lcur[t]  = c;
        gbase[t] = (c > 0) ? atomicAdd(&g_cursor[t], c) : 0;
    }
    __syncthreads();

    const int w = t >> 5, lane = t & 31;
    for (int b = w; b < NB; b += 16) {
        const int c  = lcur[b];
        const int gb = gbase[b];
        const long long gp0 = (long long)b * CAP;
        for (int j = lane; j < c; j += 32)
            __stcs(&g_binned[gp0 + min(gb + j, CAP - 1)], region[b * REG_CAP + j]);
    }
}

// ---------------------------------------------------------------- degree (split, batch-4)
__global__ __launch_bounds__(512) void k_cnt(int nb) {
    __shared__ int cnt[SLICE];
    const int b    = blockIdx.x / SPLIT;
    const int part = blockIdx.x % SPLIT;
    const int t    = threadIdx.x;
    for (int i = t; i < SLICE; i += 512) cnt[i] = 0;
    __syncthreads();

    const int ne = min(g_cursor[b], CAP);
    const int s0 = (int)((long long)ne * part / SPLIT);
    const int s1 = (int)((long long)ne * (part + 1) / SPLIT);
    const int* eb = g_binned + (size_t)b * CAP;

    int i = s0 + t;
    for (; i + 3 * 512 < s1; i += 4 * 512) {
        int pk0 = __ldcs(&eb[i]);
        int pk1 = __ldcs(&eb[i + 512]);
        int pk2 = __ldcs(&eb[i + 1024]);
        int pk3 = __ldcs(&eb[i + 1536]);
        atomicAdd(&cnt[(pk0 >> 19) & (SLICE - 1)], 1);
        atomicAdd(&cnt[(pk1 >> 19) & (SLICE - 1)], 1);
        atomicAdd(&cnt[(pk2 >> 19) & (SLICE - 1)], 1);
        atomicAdd(&cnt[(pk3 >> 19) & (SLICE - 1)], 1);
    }
    for (; i < s1; i += 512)
        atomicAdd(&cnt[(__ldcs(&eb[i]) >> 19) & (SLICE - 1)], 1);
    __syncthreads();

    const int nbase = b << SHIFT;
    for (int l = t; l < SLICE; l += 512)
        if (cnt[l]) atomicAdd(&g_cnt[nbase + l], cnt[l]);
}

// ---------------------------------------------------------------- node A: dis, p
__global__ void k_nodeA(const float* __restrict__ x, int N) {
    int i = blockIdx.x * blockDim.x + threadIdx.x;
    if (i < N) {
        float dis = rsqrtf((float)(g_cnt[i] + 1));   // +1 self loop
        g_dis[i] = dis;
        g_p[i]   = dis * x[i];
    }
}

// ---------------------------------------------------------------- layer-1 scatter (split, batch-8)
__global__ __launch_bounds__(512) void k_s1(int nb) {
    __shared__ float acc[SLICE];
    const int b    = blockIdx.x / SPLIT;
    const int part = blockIdx.x % SPLIT;
    const int t    = threadIdx.x;
    for (int i = t; i < SLICE; i += 512) acc[i] = 0.0f;
    __syncthreads();

    const int ne = min(g_cursor[b], CAP);
    const int s0 = (int)((long long)ne * part / SPLIT);
    const int s1 = (int)((long long)ne * (part + 1) / SPLIT);
    const int* eb = g_binned + (size_t)b * CAP;

    int i = s0 + t;
    for (; i + 7 * 512 < s1; i += 8 * 512) {
        int pk[8];
        float p[8];
#pragma unroll
        for (int u = 0; u < 8; u++) pk[u] = __ldcs(&eb[i + u * 512]);
#pragma unroll
        for (int u = 0; u < 8; u++) p[u] = __ldg(&g_p[pk[u] & 0x7FFFF]);
#pragma unroll
        for (int u = 0; u < 8; u++)
            atomicAdd(&acc[(pk[u] >> 19) & (SLICE - 1)], p[u]);
    }
    for (; i < s1; i += 512) {
        int pk = __ldcs(&eb[i]);
        atomicAdd(&acc[(pk >> 19) & (SLICE - 1)], __ldg(&g_p[pk & 0x7FFFF]));
    }
    __syncthreads();

    const int nbase = b << SHIFT;
    for (int l = t; l < SLICE; l += 512)
        if (acc[l] != 0.0f) atomicAdd(&g_t[nbase + l], acc[l]);
}

// ---------------------------------------------------------------- node B: MLP -> q, out0
__global__ void k_nodeB(const float* __restrict__ x,
                        const float* __restrict__ W1,
                        const float* __restrict__ b1,
                        const float* __restrict__ W2,
                        const float* __restrict__ b2,
                        float2* __restrict__ out, int N) {
    int i = blockIdx.x * blockDim.x + threadIdx.x;
    if (i >= N) return;
    float dis = g_dis[i];
    float s   = dis * (g_t[i] + dis * x[i]);
    float q0 = 0.0f, q1 = 0.0f;
#pragma unroll
    for (int k = 0; k < 8; k++) {
        float h = fmaxf(fmaf(s, __ldg(&W1[k]), __ldg(&b1[k])), 0.0f);
        q0 = fmaf(h, __ldg(&W2[2 * k + 0]), q0);
        q1 = fmaf(h, __ldg(&W2[2 * k + 1]), q1);
    }
    q0 *= dis; q1 *= dis;
    g_q[i] = make_float2(q0, q1);
    // out0 = dis*q_i + b2 (self-loop term + bias); s2 adds dis*sum(q_j)
    out[i] = make_float2(fmaf(dis, q0, __ldg(&b2[0])),
                         fmaf(dis, q1, __ldg(&b2[1])));
}

// ---------------------------------------------------------------- layer-2 scatter (split, batch-8) -> out
__device__ __forceinline__ void red_add_v2(float2* addr, float a, float b) {
    asm volatile("red.global.add.v2.f32 [%0], {%1, %2};"
                 :: "l"(addr), "f"(a), "f"(b) : "memory");
}

__global__ __launch_bounds__(512) void k_s2(float2* __restrict__ out, int N) {
    __shared__ float ux[SLICE];
    __shared__ float uy[SLICE];
    const int b    = blockIdx.x / SPLIT;
    const int part = blockIdx.x % SPLIT;
    const int t    = threadIdx.x;
    for (int i = t; i < SLICE; i += 512) { ux[i] = 0.0f; uy[i] = 0.0f; }
    __syncthreads();

    const int ne = min(g_cursor[b], CAP);
    const int s0 = (int)((long long)ne * part / SPLIT);
    const int s1 = (int)((long long)ne * (part + 1) / SPLIT);
    const int* eb = g_binned + (size_t)b * CAP;

    int i = s0 + t;
    for (; i + 7 * 512 < s1; i += 8 * 512) {
        int pk[8];
        float2 q[8];
#pragma unroll
        for (int u = 0; u < 8; u++) pk[u] = __ldcs(&eb[i + u * 512]);
#pragma unroll
        for (int u = 0; u < 8; u++) q[u] = __ldg(&g_q[pk[u] & 0x7FFFF]);
#pragma unroll
        for (int u = 0; u < 8; u++) {
            int l = (pk[u] >> 19) & (SLICE - 1);
            atomicAdd(&ux[l], q[u].x);
            atomicAdd(&uy[l], q[u].y);
        }
    }
    for (; i < s1; i += 512) {
        int pk = __ldcs(&eb[i]);
        float2 q = __ldg(&g_q[pk & 0x7FFFF]);
        int l = (pk >> 19) & (SLICE - 1);
        atomicAdd(&ux[l], q.x); atomicAdd(&uy[l], q.y);
    }
    __syncthreads();

    const int nbase = b << SHIFT;
    for (int l = t; l < SLICE; l += 512) {
        int node = nbase + l;
        if (node < N && (ux[l] != 0.0f || uy[l] != 0.0f)) {
            float dis = g_dis[node];
            red_add_v2(&out[node], dis * ux[l], dis * uy[l]);
        }
    }
}

// ================================================================ launch
extern "C" void kernel_launch(void* const* d_in, const int* in_sizes, int n_in,
                              void* d_out, int out_size) {
    const float* x  = (const float*)d_in[0];
    const void*  ei = d_in[1];            // [2, E]: src then dst; int32 or int64
    const float* W1 = (const float*)d_in[2];
    const float* b1 = (const float*)d_in[3];
    const float* W2 = (const float*)d_in[4];
    const float* b2 = (const float*)d_in[5];

    const int N  = in_sizes[0];           // 500000
    const int E  = in_sizes[1] / 2;       // 16000000
    int nb = (N + SLICE - 1) >> SHIFT;    // 123
    if (nb > NB) nb = NB;

    const int nb_bin  = (int)(((long long)E + CHUNK - 1) / CHUNK);
    const int nb_node = (N + 255) / 256;

    k_detect<<<1, 128>>>((const long long*)ei, 64, N);
    k_zero  <<<nb_node, 256>>>(N);
    k_bin   <<<nb_bin, BT>>>(ei, E);
    k_cnt   <<<nb * SPLIT, 512>>>(nb);
    k_nodeA <<<nb_node, 256>>>(x, N);
    k_s1    <<<nb * SPLIT, 512>>>(nb);
    k_nodeB <<<nb_node, 256>>>(x, W1, b1, W2, b2, (float2*)d_out, N);
    k_s2    <<<nb * SPLIT, 512>>>((float2*)d_out, N);
}

// round 11
// speedup vs baseline: 1.0761x; 1.0085x over previous
#include <cuda_runtime.h>
#include <cuda_bf16.h>
#include <cstdint>

// GCN 2-layer, N=500000, E=16000000 — SRC-binned formulation, v9.
//
//   deg_i = indeg(i) + 1;  dis_i = rsqrt(deg_i);  p_j = dis_j * x_j
//   s_i = dis_i * ( sum_{j->i} p_j + dis_i*x_i )
//   h_i[k] = relu(s_i*W1[k] + b1[k]);  q_i = dis_i * (h_i @ W2)
//   out_i = dis_i * ( sum_{j->i} q_j + q_i ) + b2
//
// Edges binned by SRC>>12 (123 buckets): pk = dst | ((src&4095) << 19).
// Consumers load the bucket's p/q slice into smem (contiguous) and scatter
// per-edge contributions with fire-and-forget red.global.add — no random
// gathers anywhere. Degree counting rides inside k_bin as int REDs.

static constexpr int N_MAX   = 500000;
static constexpr int SHIFT   = 12;
static constexpr int SLICE   = 1 << SHIFT;           // 4096
static constexpr int NB      = 128;                  // >= ceil(500000/4096)=123
static constexpr int NPAD    = NB * SLICE;           // 524288 (padded node arrays)
static constexpr int CAP     = 139264;               // mean 130081 + ~25 sigma
static constexpr int BT      = 512;                  // bin threads
static constexpr int PER     = 8;                    // edges per bin thread
static constexpr int CHUNK   = BT * PER;             // 4096
static constexpr int REG_CAP = 80;                   // mean 32/bucket + 8.4 sigma
static constexpr int SPLIT   = 8;                    // CTAs per bucket

__device__ int    g_is64;
__device__ int    g_cursor[NB];
__device__ int    g_binned[(size_t)NB * CAP];        // packed edges (~71 MB)
__device__ int    g_cnt[NPAD];                       // indegree
__device__ float  g_t[NPAD];                         // layer-1 accumulator
__device__ float2 g_U[NPAD];                         // layer-2 accumulator
__device__ float  g_dis[NPAD];
__device__ float  g_p[NPAD];                         // dis_j * x_j
__device__ float2 g_q[NPAD];                         // dis_i * (h_i @ W2)

__device__ __forceinline__ void red_add_s32(int* addr, int v) {
    asm volatile("red.global.add.s32 [%0], %1;" :: "l"(addr), "r"(v) : "memory");
}
__device__ __forceinline__ void red_add_f32(float* addr, float v) {
    asm volatile("red.global.add.f32 [%0], %1;" :: "l"(addr), "f"(v) : "memory");
}
__device__ __forceinline__ void red_add_v2(float2* addr, float a, float b) {
    asm volatile("red.global.add.v2.f32 [%0], {%1, %2};"
                 :: "l"(addr), "f"(a), "f"(b) : "memory");
}

// ---------------------------------------------------------------- init: zero + dtype probe
__global__ void k_init(const long long* __restrict__ ei, int n_check, int N) {
    int i = blockIdx.x * blockDim.x + threadIdx.x;
    if (i < NPAD) {
        g_cnt[i] = 0;
        g_t[i]   = 0.0f;
        g_U[i]   = make_float2(0.0f, 0.0f);
    }
    if (i < NB) g_cursor[i] = 0;
    if (i == 0) {
        int ok = 1;
        for (int k = 0; k < n_check; k++) {
            long long v = ei[k];
            if (v < 0 || v >= (long long)N) { ok = 0; break; }
        }
        g_is64 = ok;
    }
}

// ---------------------------------------------------------------- binning by src (+deg REDs)
__global__ __launch_bounds__(BT) void k_bin(const void* __restrict__ edge, int E) {
    __shared__ int region[NB * REG_CAP];   // 40 KB
    __shared__ int lcur[NB];
    __shared__ int gbase[NB];

    const int t = threadIdx.x;
    const long long base = (long long)blockIdx.x * CHUNK;
    if (base >= E) return;

    if (t < NB) lcur[t] = 0;
    __syncthreads();

    const bool is64 = (g_is64 != 0);
    if (is64) {
        const long long* src = (const long long*)edge;
        const long long* dst = src + E;
#pragma unroll
        for (int k = 0; k < PER; k++) {
            long long idx = base + k * BT + t;
            if (idx < E) {
                int s = (int)__ldcs(&src[idx]);
                int d = (int)__ldcs(&dst[idx]);
                red_add_s32(&g_cnt[d], 1);                  // degree, fire-forget
                int b = s >> SHIFT;
                int pos = atomicAdd(&lcur[b], 1);
                if (pos < REG_CAP)
                    region[b * REG_CAP + pos] = d | ((s & (SLICE - 1)) << 19);
            }
        }
    } else {
        const int* src = (const int*)edge;
        const int* dst = src + E;
#pragma unroll
        for (int k = 0; k < PER; k++) {
            long long idx = base + k * BT + t;
            if (idx < E) {
                int s = __ldcs(&src[idx]);
                int d = __ldcs(&dst[idx]);
                red_add_s32(&g_cnt[d], 1);                  // degree, fire-forget
                int b = s >> SHIFT;
                int pos = atomicAdd(&lcur[b], 1);
                if (pos < REG_CAP)
                    region[b * REG_CAP + pos] = d | ((s & (SLICE - 1)) << 19);
            }
        }
    }
    __syncthreads();

    if (t < NB) {
        int c = min(lcur[t], REG_CAP);
        lcur[t]  = c;
        gbase[t] = (c > 0) ? atomicAdd(&g_cursor[t], c) : 0;
    }
    __syncthreads();

    const int w = t >> 5, lane = t & 31;
    for (int b = w; b < NB; b += 16) {
        const int c  = lcur[b];
        const int gb = gbase[b];
        const long long gp0 = (long long)b * CAP;
        for (int j = lane; j < c; j += 32)
            __stcs(&g_binned[gp0 + min(gb + j, CAP - 1)], region[b * REG_CAP + j]);
    }
}

// ---------------------------------------------------------------- node A: dis, p
__global__ void k_nodeA(const float* __restrict__ x, int N) {
    int i = blockIdx.x * blockDim.x + threadIdx.x;
    if (i < NPAD) {
        float xv  = (i < N) ? x[i] : 0.0f;
        float dis = rsqrtf((float)(g_cnt[i] + 1));   // +1 self loop
        g_dis[i] = dis;
        g_p[i]   = dis * xv;
    }
}

// ---------------------------------------------------------------- layer-1 scatter: smem p-slice -> REDs
__global__ __launch_bounds__(512) void k_s1(int nb) {
    __shared__ float p_s[SLICE];          // 16 KB
    const int b    = blockIdx.x / SPLIT;
    const int part = blockIdx.x % SPLIT;
    const int t    = threadIdx.x;
    const int nbase = b << SHIFT;
    for (int l = t; l < SLICE; l += 512) p_s[l] = g_p[nbase + l];
    __syncthreads();

    const int ne = min(g_cursor[b], CAP);
    const int s0 = (int)((long long)ne * part / SPLIT);
    const int s1 = (int)((long long)ne * (part + 1) / SPLIT);
    const int* eb = g_binned + (size_t)b * CAP;

    int i = s0 + t;
    for (; i + 3 * 512 < s1; i += 4 * 512) {
        int pk0 = __ldcs(&eb[i]);
        int pk1 = __ldcs(&eb[i + 512]);
        int pk2 = __ldcs(&eb[i + 1024]);
        int pk3 = __ldcs(&eb[i + 1536]);
        red_add_f32(&g_t[pk0 & 0x7FFFF], p_s[(pk0 >> 19) & (SLICE - 1)]);
        red_add_f32(&g_t[pk1 & 0x7FFFF], p_s[(pk1 >> 19) & (SLICE - 1)]);
        red_add_f32(&g_t[pk2 & 0x7FFFF], p_s[(pk2 >> 19) & (SLICE - 1)]);
        red_add_f32(&g_t[pk3 & 0x7FFFF], p_s[(pk3 >> 19) & (SLICE - 1)]);
    }
    for (; i < s1; i += 512) {
        int pk = __ldcs(&eb[i]);
        red_add_f32(&g_t[pk & 0x7FFFF], p_s[(pk >> 19) & (SLICE - 1)]);
    }
}

// ---------------------------------------------------------------- node B: MLP -> q
__global__ void k_nodeB(const float* __restrict__ x,
                        const float* __restrict__ W1,
                        const float* __restrict__ b1,
                        const float* __restrict__ W2, int N) {
    int i = blockIdx.x * blockDim.x + threadIdx.x;
    if (i >= NPAD) return;
    float dis = g_dis[i];
    float xv  = (i < N) ? x[i] : 0.0f;
    float s   = dis * (g_t[i] + dis * xv);
    float q0 = 0.0f, q1 = 0.0f;
#pragma unroll
    for (int k = 0; k < 8; k++) {
        float h = fmaxf(fmaf(s, __ldg(&W1[k]), __ldg(&b1[k])), 0.0f);
        q0 = fmaf(h, __ldg(&W2[2 * k + 0]), q0);
        q1 = fmaf(h, __ldg(&W2[2 * k + 1]), q1);
    }
    g_q[i] = make_float2(dis * q0, dis * q1);
}

// ---------------------------------------------------------------- layer-2 scatter: smem q-slice -> REDs
__global__ __launch_bounds__(512) void k_s2(int nb) {
    __shared__ float2 q_s[SLICE];         // 32 KB
    const int b    = blockIdx.x / SPLIT;
    const int part = blockIdx.x % SPLIT;
    const int t    = threadIdx.x;
    const int nbase = b << SHIFT;
    for (int l = t; l < SLICE; l += 512) q_s[l] = g_q[nbase + l];
    __syncthreads();

    const int ne = min(g_cursor[b], CAP);
    const int s0 = (int)((long long)ne * part / SPLIT);
    const int s1 = (int)((long long)ne * (part + 1) / SPLIT);
    const int* eb = g_binned + (size_t)b * CAP;

    int i = s0 + t;
    for (; i + 3 * 512 < s1; i += 4 * 512) {
        int pk0 = __ldcs(&eb[i]);
        int pk1 = __ldcs(&eb[i + 512]);
        int pk2 = __ldcs(&eb[i + 1024]);
        int pk3 = __ldcs(&eb[i + 1536]);
        float2 q0 = q_s[(pk0 >> 19) & (SLICE - 1)];
        float2 q1 = q_s[(pk1 >> 19) & (SLICE - 1)];
        float2 q2 = q_s[(pk2 >> 19) & (SLICE - 1)];
        float2 q3 = q_s[(pk3 >> 19) & (SLICE - 1)];
        red_add_v2(&g_U[pk0 & 0x7FFFF], q0.x, q0.y);
        red_add_v2(&g_U[pk1 & 0x7FFFF], q1.x, q1.y);
        red_add_v2(&g_U[pk2 & 0x7FFFF], q2.x, q2.y);
        red_add_v2(&g_U[pk3 & 0x7FFFF], q3.x, q3.y);
    }
    for (; i < s1; i += 512) {
        int pk = __ldcs(&eb[i]);
        float2 q = q_s[(pk >> 19) & (SLICE - 1)];
        red_add_v2(&g_U[pk & 0x7FFFF], q.x, q.y);
    }
}

// ---------------------------------------------------------------- epilogue
__global__ void k_final(const float* __restrict__ b2, float2* __restrict__ out, int N) {
    int i = blockIdx.x * blockDim.x + threadIdx.x;
    if (i >= N) return;
    float  dis = g_dis[i];
    float2 q   = g_q[i];
    float2 U   = g_U[i];
    out[i] = make_float2(fmaf(dis, U.x + q.x, __ldg(&b2[0])),
                         fmaf(dis, U.y + q.y, __ldg(&b2[1])));
}

// ================================================================ launch
extern "C" void kernel_launch(void* const* d_in, const int* in_sizes, int n_in,
                              void* d_out, int out_size) {
    const float* x  = (const float*)d_in[0];
    const void*  ei = d_in[1];            // [2, E]: src then dst; int32 or int64
    const float* W1 = (const float*)d_in[2];
    const float* b1 = (const float*)d_in[3];
    const float* W2 = (const float*)d_in[4];
    const float* b2 = (const float*)d_in[5];

    const int N  = in_sizes[0];           // 500000
    const int E  = in_sizes[1] / 2;       // 16000000
    int nb = (N + SLICE - 1) >> SHIFT;    // 123
    if (nb > NB) nb = NB;

    const int nb_bin  = (int)(((long long)E + CHUNK - 1) / CHUNK);
    const int nb_pad  = (NPAD + 255) / 256;
    const int nb_node = (N + 255) / 256;

    k_init <<<nb_pad, 256>>>((const long long*)ei, 64, N);
    k_bin  <<<nb_bin, BT>>>(ei, E);
    k_nodeA<<<nb_pad, 256>>>(x, N);
    k_s1   <<<nb * SPLIT, 512>>>(nb);
    k_nodeB<<<nb_pad, 256>>>(x, W1, b1, W2, N);
    k_s2   <<<nb * SPLIT, 512>>>(nb);
    k_final<<<nb_node, 256>>>(b2, (float2*)d_out, N);
}